// round 2
// baseline (speedup 1.0000x reference)
#include <cuda_runtime.h>
#include <cuda_bf16.h>
#include <cstdint>

// Problem: StatsQuantizer forward.
//   W: [8192, 8192] fp32 (d_in[0]), clip_val: [1] fp32 (d_in[1]) == 2.0
//   sf[r] = 2*mean(|W[r,:]|)
//   out   = sf * (rint(clamp(W/sf, -clip/2, clip/2 - 1e-6)*8 - 0.5) + 0.5) / 8
// Freeze-mask logic in the reference is value-neutral (gradient-only), so the
// forward output is exactly the expression above.
//
// Strategy: one CTA per row. 256 threads x 8 float4 = 8192 floats held in
// registers; block-reduce |.| sum; apply quantization; write back. Single
// pass over HBM: 256 MB read + 256 MB write.

#define ROW_LEN   8192
#define THREADS   256
#define V4_PER_T  8          // 8192 floats / 4 / 256 threads

__global__ __launch_bounds__(THREADS, 4)
void statsquant_kernel(const float* __restrict__ w,
                       const float* __restrict__ clip_val,
                       float* __restrict__ out)
{
    const int row = blockIdx.x;
    const size_t base = (size_t)row * ROW_LEN;
    const float4* __restrict__ wrow = reinterpret_cast<const float4*>(w + base);
    float4* __restrict__ orow = reinterpret_cast<float4*>(out + base);

    const int t = threadIdx.x;

    // ---- Load full row into registers, accumulate |.| sum ----
    float4 v[V4_PER_T];
    float s = 0.0f;
#pragma unroll
    for (int i = 0; i < V4_PER_T; ++i) {
        v[i] = wrow[t + i * THREADS];
        s += fabsf(v[i].x) + fabsf(v[i].y) + fabsf(v[i].z) + fabsf(v[i].w);
    }

    // ---- Block reduction (8 warps) ----
    __shared__ float red[8];
#pragma unroll
    for (int o = 16; o > 0; o >>= 1)
        s += __shfl_xor_sync(0xffffffffu, s, o);
    if ((t & 31) == 0) red[t >> 5] = s;
    __syncthreads();
    if (t < 32) {
        float r2 = (t < 8) ? red[t] : 0.0f;
#pragma unroll
        for (int o = 4; o > 0; o >>= 1)
            r2 += __shfl_xor_sync(0xffffffffu, r2, o);
        if (t == 0) red[0] = r2;
    }
    __syncthreads();

    // sf = 2 * mean = 2 * sum / 8192 = sum / 4096
    const float sf     = red[0] * (1.0f / 4096.0f);
    const float inv_sf = 1.0f / sf;

    const float hc = 0.5f * clip_val[0];
    const float lo = -hc;
    const float hi = hc - 1e-6f;
    const float out_scale = sf * 0.125f;   // sf / n, n = 8

    // ---- Quantize + store ----
#pragma unroll
    for (int i = 0; i < V4_PER_T; ++i) {
        float4 q;
        {
            float c = fminf(fmaxf(v[i].x * inv_sf, lo), hi);
            q.x = (rintf(fmaf(c, 8.0f, -0.5f)) + 0.5f) * out_scale;
        }
        {
            float c = fminf(fmaxf(v[i].y * inv_sf, lo), hi);
            q.y = (rintf(fmaf(c, 8.0f, -0.5f)) + 0.5f) * out_scale;
        }
        {
            float c = fminf(fmaxf(v[i].z * inv_sf, lo), hi);
            q.z = (rintf(fmaf(c, 8.0f, -0.5f)) + 0.5f) * out_scale;
        }
        {
            float c = fminf(fmaxf(v[i].w * inv_sf, lo), hi);
            q.w = (rintf(fmaf(c, 8.0f, -0.5f)) + 0.5f) * out_scale;
        }
        orow[t + i * THREADS] = q;
    }
}

extern "C" void kernel_launch(void* const* d_in, const int* in_sizes, int n_in,
                              void* d_out, int out_size)
{
    const float* w    = (const float*)d_in[0];
    const float* clip = (const float*)d_in[1];
    float* out        = (float*)d_out;
    (void)in_sizes; (void)n_in; (void)out_size;

    statsquant_kernel<<<ROW_LEN, THREADS>>>(w, clip, out);
}

// round 3
// speedup vs baseline: 1.0164x; 1.0164x over previous
#include <cuda_runtime.h>
#include <cuda_bf16.h>
#include <cstdint>

// StatsQuantizer forward, fused single-pass.
//   sf[r] = 2*mean(|W[r,:]|) = sum(|W[r,:]|)/4096
//   out   = sf * (rint(clamp(W/sf, -clip/2, clip/2-1e-6)*8 - 0.5) + 0.5) / 8
//
// R2: 512 threads/CTA, 4 float4 per thread (16 data regs) -> ~75% occupancy
// (3 CTAs x 16 warps) so concurrent CTAs cover each other's reduction-barrier
// bubbles. Streaming load/store hints (single-use data, no reuse).

#define ROW_LEN   8192
#define THREADS   512
#define V4_PER_T  4          // 8192 / 4 / 512

__global__ __launch_bounds__(THREADS, 3)
void statsquant_kernel(const float* __restrict__ w,
                       const float* __restrict__ clip_val,
                       float* __restrict__ out)
{
    const int row = blockIdx.x;
    const size_t base = (size_t)row * ROW_LEN;
    const float4* __restrict__ wrow = reinterpret_cast<const float4*>(w + base);
    float4* __restrict__ orow = reinterpret_cast<float4*>(out + base);

    const int t = threadIdx.x;

    // ---- Load row slice into registers (streaming), accumulate |.| ----
    float4 v[V4_PER_T];
    float s = 0.0f;
#pragma unroll
    for (int i = 0; i < V4_PER_T; ++i) {
        v[i] = __ldcs(&wrow[t + i * THREADS]);
        s += fabsf(v[i].x) + fabsf(v[i].y) + fabsf(v[i].z) + fabsf(v[i].w);
    }

    // ---- Block reduction (16 warps) ----
    __shared__ float red[16];
#pragma unroll
    for (int o = 16; o > 0; o >>= 1)
        s += __shfl_xor_sync(0xffffffffu, s, o);
    if ((t & 31) == 0) red[t >> 5] = s;
    __syncthreads();
    if (t < 32) {
        float r2 = (t < 16) ? red[t] : 0.0f;
#pragma unroll
        for (int o = 8; o > 0; o >>= 1)
            r2 += __shfl_xor_sync(0xffffffffu, r2, o);
        if (t == 0) red[0] = r2;
    }
    __syncthreads();

    const float sf     = red[0] * (1.0f / 4096.0f);
    const float inv_sf = 1.0f / sf;

    const float hc = 0.5f * clip_val[0];
    const float lo = -hc;
    const float hi = hc - 1e-6f;
    const float out_scale = sf * 0.125f;

    // ---- Quantize + streaming store ----
#pragma unroll
    for (int i = 0; i < V4_PER_T; ++i) {
        float4 q;
        {
            float c = fminf(fmaxf(v[i].x * inv_sf, lo), hi);
            q.x = (rintf(fmaf(c, 8.0f, -0.5f)) + 0.5f) * out_scale;
        }
        {
            float c = fminf(fmaxf(v[i].y * inv_sf, lo), hi);
            q.y = (rintf(fmaf(c, 8.0f, -0.5f)) + 0.5f) * out_scale;
        }
        {
            float c = fminf(fmaxf(v[i].z * inv_sf, lo), hi);
            q.z = (rintf(fmaf(c, 8.0f, -0.5f)) + 0.5f) * out_scale;
        }
        {
            float c = fminf(fmaxf(v[i].w * inv_sf, lo), hi);
            q.w = (rintf(fmaf(c, 8.0f, -0.5f)) + 0.5f) * out_scale;
        }
        __stcs(&orow[t + i * THREADS], q);
    }
}

extern "C" void kernel_launch(void* const* d_in, const int* in_sizes, int n_in,
                              void* d_out, int out_size)
{
    const float* w    = (const float*)d_in[0];
    const float* clip = (const float*)d_in[1];
    float* out        = (float*)d_out;
    (void)in_sizes; (void)n_in; (void)out_size;

    statsquant_kernel<<<ROW_LEN, THREADS>>>(w, clip, out);
}